// round 1
// baseline (speedup 1.0000x reference)
#include <cuda_runtime.h>

// Per-batch integer accumulators (N=64): sums of R*i (y), R*j (x), and peak counts.
__device__ int g_sum_y[64];
__device__ int g_sum_x[64];
__device__ int g_cnt[64];

__global__ void init_kernel() {
    int t = threadIdx.x;
    if (t < 64) { g_sum_y[t] = 0; g_sum_x[t] = 0; g_cnt[t] = 0; }
}

// One thread per interior pixel. Strict > over all 8 neighbors.
// blockDim = (32, 8): each warp is one row of the tile.
__global__ void peak_kernel(const float* __restrict__ p, int H, int W, int R) {
    const int n = blockIdx.z;
    const float* __restrict__ h = p + ((size_t)n * 3 + 2) * (size_t)H * W;

    const int j = blockIdx.x * 32 + threadIdx.x + 1;
    const int i = blockIdx.y * 8 + threadIdx.y + 1;

    int sy = 0, sx = 0, sc = 0;
    if (i <= H - 2 && j <= W - 2) {
        const float* b = h + (size_t)i * W + j;
        const float c = b[0];
        bool peak =
            (c > __ldg(b - W - 1)) & (c > __ldg(b - W)) & (c > __ldg(b - W + 1)) &
            (c > __ldg(b - 1))     &                       (c > __ldg(b + 1))     &
            (c > __ldg(b + W - 1)) & (c > __ldg(b + W)) & (c > __ldg(b + W + 1));
        if (peak) { sy = i; sx = j; sc = 1; }
    }

    // Warp reduction (each warp = one tile row since blockDim.x == 32)
    sy = __reduce_add_sync(0xFFFFFFFFu, sy);
    sx = __reduce_add_sync(0xFFFFFFFFu, sx);
    sc = __reduce_add_sync(0xFFFFFFFFu, sc);

    __shared__ int ssy[8], ssx[8], ssc[8];
    if (threadIdx.x == 0) {
        ssy[threadIdx.y] = sy; ssx[threadIdx.y] = sx; ssc[threadIdx.y] = sc;
    }
    __syncthreads();

    if (threadIdx.y == 0) {
        int vy = (threadIdx.x < 8) ? ssy[threadIdx.x] : 0;
        int vx = (threadIdx.x < 8) ? ssx[threadIdx.x] : 0;
        int vc = (threadIdx.x < 8) ? ssc[threadIdx.x] : 0;
        vy = __reduce_add_sync(0xFFFFFFFFu, vy);
        vx = __reduce_add_sync(0xFFFFFFFFu, vx);
        vc = __reduce_add_sync(0xFFFFFFFFu, vc);
        if (threadIdx.x == 0) {
            if (vc) {
                atomicAdd(&g_sum_y[n], R * vy);
                atomicAdd(&g_sum_x[n], R * vx);
                atomicAdd(&g_cnt[n], vc);
            }
        }
    }
}

// 64 threads (one per batch). Computes target center sums, smooth-L1, final loss.
__global__ void finalize_kernel(const float* __restrict__ target, float* __restrict__ out) {
    const int n = threadIdx.x;  // 0..63

    // truths_sum[n][0] uses target coords (0,2); [1] uses (1,3). boxes = target[:,:,:4].
    const float* t = target + (size_t)n * 32 * 5;
    float t0 = 0.f, t1 = 0.f;
#pragma unroll 4
    for (int k = 0; k < 32; k++) {
        const float* b = t + k * 5;
        t0 += (b[0] + b[2]) * 0.5f;
        t1 += (b[1] + b[3]) * 0.5f;
    }

    const float c0 = (float)g_sum_y[n];  // center_sum[:,0]
    const float c1 = (float)g_sum_x[n];  // center_sum[:,1]
    const int   cn = g_cnt[n];

    float d0 = fabsf(c0 - t0);
    float d1 = fabsf(c1 - t1);
    float l0 = (d0 < 1.f) ? 0.5f * d0 * d0 : d0 - 0.5f;  // contribution to off_x
    float l1 = (d1 < 1.f) ? 0.5f * d1 * d1 : d1 - 0.5f;  // contribution to off_y

    // Reduce 6 quantities over 64 threads (2 warps).
    float off0 = l0, off1 = l1, cs0 = c0, cs1 = c1, ts0 = t0, ts1 = t1;
    int cnt = cn;
#pragma unroll
    for (int d = 16; d > 0; d >>= 1) {
        off0 += __shfl_down_sync(0xFFFFFFFFu, off0, d);
        off1 += __shfl_down_sync(0xFFFFFFFFu, off1, d);
        cs0  += __shfl_down_sync(0xFFFFFFFFu, cs0, d);
        cs1  += __shfl_down_sync(0xFFFFFFFFu, cs1, d);
        ts0  += __shfl_down_sync(0xFFFFFFFFu, ts0, d);
        ts1  += __shfl_down_sync(0xFFFFFFFFu, ts1, d);
        cnt  += __shfl_down_sync(0xFFFFFFFFu, cnt, d);
    }
    __shared__ float sh[2][6];
    __shared__ int shc[2];
    const int w = n >> 5;
    if ((n & 31) == 0) {
        sh[w][0] = off0; sh[w][1] = off1; sh[w][2] = cs0;
        sh[w][3] = cs1;  sh[w][4] = ts0;  sh[w][5] = ts1;
        shc[w] = cnt;
    }
    __syncthreads();
    if (n == 0) {
        float OFF0 = sh[0][0] + sh[1][0];
        float OFF1 = sh[0][1] + sh[1][1];
        float CS0  = sh[0][2] + sh[1][2];
        float CS1  = sh[0][3] + sh[1][3];
        float TS0  = sh[0][4] + sh[1][4];
        float TS1  = sh[0][5] + sh[1][5];
        float PSUM = (float)(shc[0] + shc[1]);
        float loss = (OFF0 / fabsf(OFF0) * (CS0 - TS0) +
                      OFF1 / fabsf(OFF1) * (CS1 - TS1)) / PSUM;
        out[0] = loss;
    }
}

extern "C" void kernel_launch(void* const* d_in, const int* in_sizes, int n_in,
                              void* d_out, int out_size) {
    const float *p1 = nullptr, *p2 = nullptr, *p3 = nullptr, *tg = nullptr;
    for (int k = 0; k < n_in; k++) {
        switch (in_sizes[k]) {
            case 64 * 3 * 256 * 256: p1 = (const float*)d_in[k]; break;
            case 64 * 3 * 128 * 128: p2 = (const float*)d_in[k]; break;
            case 64 * 3 * 64 * 64:   p3 = (const float*)d_in[k]; break;
            case 64 * 32 * 5:        tg = (const float*)d_in[k]; break;
            default: break;
        }
    }

    init_kernel<<<1, 128>>>();
    dim3 blk(32, 8);
    // interiors: 254x254, 126x126, 62x62
    peak_kernel<<<dim3(8, 32, 64), blk>>>(p1, 256, 256, 4);
    peak_kernel<<<dim3(4, 16, 64), blk>>>(p2, 128, 128, 8);
    peak_kernel<<<dim3(2,  8, 64), blk>>>(p3,  64,  64, 16);
    finalize_kernel<<<1, 64>>>(tg, (float*)d_out);
}

// round 3
// speedup vs baseline: 2.9356x; 2.9356x over previous
#include <cuda_runtime.h>

// Per-batch exact integer accumulators: [n] = {sum_y(=Σ R*i), sum_x(=Σ R*j), count}
// Zero-initialized at module load; finalize_kernel re-zeroes after reading so
// every graph replay starts from a clean state (deterministic).
__device__ int g_acc[64][3];

// ---------------------------------------------------------------------------
// Register-rolling 8-neighbor strict-peak detector.
// One warp-group of LANE_W lanes covers 4*LANE_W columns; rows roll through
// registers A(i-1), B(i), C(i+1). Peak(i,j) <=> B[j] > max(vAC[j], vm3[j-1], vm3[j+1]).
// ---------------------------------------------------------------------------
template<int W, int R, int LANE_W>
__device__ __forceinline__ void process_strip(
    const float* __restrict__ img,   // channel-2 base for this batch
    int n, int i_begin, int i_end, int col_base)
{
    const int lane = threadIdx.x & 31;
    const int li   = lane % LANE_W;
    const unsigned shfl_mask = (LANE_W == 32) ? 0xFFFFFFFFu
                                              : (0xFFFFu << ((lane & 16)));
    const int col0 = col_base + 4 * li;
    const bool hl = (col_base > 0) && (li == 0);               // left halo load
    const bool hr = (col_base + 4 * LANE_W < W) && (li == LANE_W - 1); // right halo
    const bool m0 = (col0 == 0);          // element 0 sits on image edge
    const bool m3 = (col0 + 3 == W - 1);  // element 3 sits on image edge

    const float* p = img + col0;

    float4 A = __ldg((const float4*)(p + (size_t)(i_begin - 1) * W));
    float4 B = __ldg((const float4*)(p + (size_t)i_begin * W));
    float aL = 0.f, bL = 0.f, aR = 0.f, bR = 0.f;
    if (hl) { aL = __ldg(p + (size_t)(i_begin - 1) * W - 1); bL = __ldg(p + (size_t)i_begin * W - 1); }
    if (hr) { aR = __ldg(p + (size_t)(i_begin - 1) * W + 4); bR = __ldg(p + (size_t)i_begin * W + 4); }

    int sy = 0, sx = 0, sc = 0;

#pragma unroll 4
    for (int i = i_begin; i <= i_end; ++i) {
        float4 C = __ldg((const float4*)(p + (size_t)(i + 1) * W));
        float cL = 0.f, cR = 0.f;
        if (hl) cL = __ldg(p + (size_t)(i + 1) * W - 1);
        if (hr) cR = __ldg(p + (size_t)(i + 1) * W + 4);

        // vertical maxes
        float vACx = fmaxf(A.x, C.x), vACy = fmaxf(A.y, C.y);
        float vACz = fmaxf(A.z, C.z), vACw = fmaxf(A.w, C.w);
        float m3x = fmaxf(vACx, B.x), m3y = fmaxf(vACy, B.y);
        float m3z = fmaxf(vACz, B.z), m3w = fmaxf(vACw, B.w);

        // neighbor column maxes from adjacent lanes (within LANE_W segment)
        float mL = __shfl_up_sync(shfl_mask, m3w, 1, LANE_W);
        float mR = __shfl_down_sync(shfl_mask, m3x, 1, LANE_W);
        if (hl) mL = fmaxf(fmaxf(aL, bL), cL);
        if (hr) mR = fmaxf(fmaxf(aR, bR), cR);

        bool pk0 = !m0 && (B.x > vACx) && (B.x > mL)  && (B.x > m3y);
        bool pk1 =        (B.y > vACy) && (B.y > m3x) && (B.y > m3z);
        bool pk2 =        (B.z > vACz) && (B.z > m3y) && (B.z > m3w);
        bool pk3 = !m3 && (B.w > vACw) && (B.w > m3z) && (B.w > mR);

        int npk = (int)pk0 + (int)pk1 + (int)pk2 + (int)pk3;
        sc += npk;
        sy += i * npk;
        sx += col0 * npk + (int)pk1 + 2 * (int)pk2 + 3 * (int)pk3;

        A = B; B = C;
        aL = bL; bL = cL;
        aR = bR; bR = cR;
    }

    // warp-wide reduction (both LANE_W=16 groups target the same batch n)
    sy = __reduce_add_sync(0xFFFFFFFFu, sy);
    sx = __reduce_add_sync(0xFFFFFFFFu, sx);
    sc = __reduce_add_sync(0xFFFFFFFFu, sc);
    if (lane == 0 && sc) {
        atomicAdd(&g_acc[n][0], R * sy);
        atomicAdd(&g_acc[n][1], R * sx);
        atomicAdd(&g_acc[n][2], sc);
    }
}

// ---------------------------------------------------------------------------
// One fused kernel for all 3 pyramid levels.
// Warp-work map (SR = 16 rows per strip):
//   w in [0,2048):    p1 (256x256): n=w>>5, sub=w&31: col_strip=sub&1, row_strip=sub>>1
//   w in [2048,2560): p2 (128x128): t=w-2048: n=t>>3, row_strip=t&7
//   w in [2560,2688): p3 (64x64):   t=w-2560: n=t>>1, rs=t&1; 2 groups of 16 lanes,
//                                   each group a 16-row segment (seg = rs*2 + group)
// ---------------------------------------------------------------------------
__global__ void __launch_bounds__(256) peak_all_kernel(
    const float* __restrict__ p1,
    const float* __restrict__ p2,
    const float* __restrict__ p3)
{
    const int w = blockIdx.x * (blockDim.x >> 5) + (threadIdx.x >> 5);

    if (w < 2048) {
        const int n = w >> 5;
        const int sub = w & 31;
        const int cs = sub & 1;
        const int rs = sub >> 1;
        const int i_begin = 1 + rs * 16;
        const int i_end = min(i_begin + 15, 254);
        const float* img = p1 + ((size_t)n * 3 + 2) * 65536;
        process_strip<256, 4, 32>(img, n, i_begin, i_end, cs * 128);
    } else if (w < 2560) {
        const int t = w - 2048;
        const int n = t >> 3;
        const int rs = t & 7;
        const int i_begin = 1 + rs * 16;
        const int i_end = min(i_begin + 15, 126);
        const float* img = p2 + ((size_t)n * 3 + 2) * 16384;
        process_strip<128, 8, 32>(img, n, i_begin, i_end, 0);
    } else {
        const int t = w - 2560;
        const int n = t >> 1;
        const int rs = t & 1;
        const int group = (threadIdx.x & 31) >> 4;
        const int seg = rs * 2 + group;
        const int i_begin = 1 + seg * 16;
        const int i_end = min(i_begin + 15, 62);
        const float* img = p3 + ((size_t)n * 3 + 2) * 4096;
        process_strip<64, 16, 16>(img, n, i_begin, i_end, 0);
    }
}

// ---------------------------------------------------------------------------
// Finalize: target center sums, smooth-L1, sign trick, scalar loss.
// 256 threads: thread t -> (n = t>>2, q = t&3), q handles 8 boxes.
// Also re-zeroes g_acc for the next graph replay.
// ---------------------------------------------------------------------------
__global__ void finalize_kernel(const float* __restrict__ target, float* __restrict__ out)
{
    const int t = threadIdx.x;      // 0..255
    const int n = t >> 2;
    const int q = t & 3;

    const float* tb = target + (size_t)n * 32 * 5 + q * 8 * 5;
    float t0 = 0.f, t1 = 0.f;
#pragma unroll
    for (int k = 0; k < 8; k++) {
        const float* b = tb + k * 5;
        t0 += (b[0] + b[2]) * 0.5f;
        t1 += (b[1] + b[3]) * 0.5f;
    }
    // sum the quad (threads n*4 .. n*4+3 are adjacent lanes)
    t0 += __shfl_xor_sync(0xFFFFFFFFu, t0, 1);
    t1 += __shfl_xor_sync(0xFFFFFFFFu, t1, 1);
    t0 += __shfl_xor_sync(0xFFFFFFFFu, t0, 2);
    t1 += __shfl_xor_sync(0xFFFFFFFFu, t1, 2);

    float off0 = 0.f, off1 = 0.f, cs0 = 0.f, cs1 = 0.f, ts0 = 0.f, ts1 = 0.f;
    int cnt = 0;
    if (q == 0) {
        const float c0 = (float)g_acc[n][0];   // center_sum[:,0]
        const float c1 = (float)g_acc[n][1];   // center_sum[:,1]
        cnt = g_acc[n][2];
        const float d0 = fabsf(c0 - t0);
        const float d1 = fabsf(c1 - t1);
        off0 = (d0 < 1.f) ? 0.5f * d0 * d0 : d0 - 0.5f;
        off1 = (d1 < 1.f) ? 0.5f * d1 * d1 : d1 - 0.5f;
        cs0 = c0; cs1 = c1; ts0 = t0; ts1 = t1;
        // restore invariant for next replay
        g_acc[n][0] = 0; g_acc[n][1] = 0; g_acc[n][2] = 0;
    }

    // block reduction over 256 threads (8 warps)
#pragma unroll
    for (int d = 16; d > 0; d >>= 1) {
        off0 += __shfl_down_sync(0xFFFFFFFFu, off0, d);
        off1 += __shfl_down_sync(0xFFFFFFFFu, off1, d);
        cs0  += __shfl_down_sync(0xFFFFFFFFu, cs0, d);
        cs1  += __shfl_down_sync(0xFFFFFFFFu, cs1, d);
        ts0  += __shfl_down_sync(0xFFFFFFFFu, ts0, d);
        ts1  += __shfl_down_sync(0xFFFFFFFFu, ts1, d);
        cnt  += __shfl_down_sync(0xFFFFFFFFu, cnt, d);
    }
    __shared__ float sh[8][6];
    __shared__ int shc[8];
    const int wid = t >> 5;
    if ((t & 31) == 0) {
        sh[wid][0] = off0; sh[wid][1] = off1; sh[wid][2] = cs0;
        sh[wid][3] = cs1;  sh[wid][4] = ts0;  sh[wid][5] = ts1;
        shc[wid] = cnt;
    }
    __syncthreads();
    if (t == 0) {
        float OFF0 = 0.f, OFF1 = 0.f, CS0 = 0.f, CS1 = 0.f, TS0 = 0.f, TS1 = 0.f;
        int CNT = 0;
#pragma unroll
        for (int wgt = 0; wgt < 8; wgt++) {
            OFF0 += sh[wgt][0]; OFF1 += sh[wgt][1]; CS0 += sh[wgt][2];
            CS1  += sh[wgt][3]; TS0  += sh[wgt][4]; TS1 += sh[wgt][5];
            CNT  += shc[wgt];
        }
        const float loss = (OFF0 / fabsf(OFF0) * (CS0 - TS0) +
                            OFF1 / fabsf(OFF1) * (CS1 - TS1)) / (float)CNT;
        out[0] = loss;
    }
}

extern "C" void kernel_launch(void* const* d_in, const int* in_sizes, int n_in,
                              void* d_out, int out_size) {
    const float *p1 = nullptr, *p2 = nullptr, *p3 = nullptr, *tg = nullptr;
    for (int k = 0; k < n_in; k++) {
        switch (in_sizes[k]) {
            case 64 * 3 * 256 * 256: p1 = (const float*)d_in[k]; break;
            case 64 * 3 * 128 * 128: p2 = (const float*)d_in[k]; break;
            case 64 * 3 * 64 * 64:   p3 = (const float*)d_in[k]; break;
            case 64 * 32 * 5:        tg = (const float*)d_in[k]; break;
            default: break;
        }
    }

    // 2688 warps total = 336 blocks * 8 warps
    peak_all_kernel<<<336, 256>>>(p1, p2, p3);
    finalize_kernel<<<1, 256>>>(tg, (float*)d_out);
}

// round 5
// speedup vs baseline: 3.4200x; 1.1650x over previous
#include <cuda_runtime.h>

// Per-batch exact integer accumulators: [n] = {sum_y(=Σ R*i), sum_x(=Σ R*j), count}
// Zero at module load; the final block re-zeroes after reading, so every graph
// replay starts clean (deterministic: integer adds are order-independent).
__device__ int g_acc[64][3];
__device__ float g_ts[64][2];   // target center sums, written by block 0 each run
__device__ int g_done;          // arrival counter, reset by the final block

// ---------------------------------------------------------------------------
// Register-rolling 8-neighbor strict-peak detector.
// One group of LANE_W lanes covers 4*LANE_W columns; rows roll through
// registers A(i-1), B(i), C(i+1). Peak(i,j) <=> B[j] > max(vAC[j], vm3[j-1], vm3[j+1]).
// ---------------------------------------------------------------------------
template<int W, int R, int LANE_W>
__device__ __forceinline__ void process_strip(
    const float* __restrict__ img,   // channel-2 base for this batch
    int n, int i_begin, int i_end, int col_base)
{
    const int lane = threadIdx.x & 31;
    const int li   = lane % LANE_W;
    const unsigned shfl_mask = (LANE_W == 32) ? 0xFFFFFFFFu
                                              : (0xFFFFu << ((lane & 16)));
    const int col0 = col_base + 4 * li;
    const bool hl = (col_base > 0) && (li == 0);                       // left halo
    const bool hr = (col_base + 4 * LANE_W < W) && (li == LANE_W - 1); // right halo
    const bool m0 = (col0 == 0);          // element 0 on image edge
    const bool m3 = (col0 + 3 == W - 1);  // element 3 on image edge

    const float* p = img + col0;

    float4 A = __ldg((const float4*)(p + (size_t)(i_begin - 1) * W));
    float4 B = __ldg((const float4*)(p + (size_t)i_begin * W));
    float aL = 0.f, bL = 0.f, aR = 0.f, bR = 0.f;
    if (hl) { aL = __ldg(p + (size_t)(i_begin - 1) * W - 1); bL = __ldg(p + (size_t)i_begin * W - 1); }
    if (hr) { aR = __ldg(p + (size_t)(i_begin - 1) * W + 4); bR = __ldg(p + (size_t)i_begin * W + 4); }

    int sy = 0, sx = 0, sc = 0;

#pragma unroll 4
    for (int i = i_begin; i <= i_end; ++i) {
        float4 C = __ldg((const float4*)(p + (size_t)(i + 1) * W));
        float cL = 0.f, cR = 0.f;
        if (hl) cL = __ldg(p + (size_t)(i + 1) * W - 1);
        if (hr) cR = __ldg(p + (size_t)(i + 1) * W + 4);

        // vertical maxes
        float vACx = fmaxf(A.x, C.x), vACy = fmaxf(A.y, C.y);
        float vACz = fmaxf(A.z, C.z), vACw = fmaxf(A.w, C.w);
        float m3x = fmaxf(vACx, B.x), m3y = fmaxf(vACy, B.y);
        float m3z = fmaxf(vACz, B.z), m3w = fmaxf(vACw, B.w);

        // neighbor-column maxes from adjacent lanes (within LANE_W segment)
        float mL = __shfl_up_sync(shfl_mask, m3w, 1, LANE_W);
        float mR = __shfl_down_sync(shfl_mask, m3x, 1, LANE_W);
        if (hl) mL = fmaxf(fmaxf(aL, bL), cL);
        if (hr) mR = fmaxf(fmaxf(aR, bR), cR);

        bool pk0 = !m0 && (B.x > vACx) && (B.x > mL)  && (B.x > m3y);
        bool pk1 =        (B.y > vACy) && (B.y > m3x) && (B.y > m3z);
        bool pk2 =        (B.z > vACz) && (B.z > m3y) && (B.z > m3w);
        bool pk3 = !m3 && (B.w > vACw) && (B.w > m3z) && (B.w > mR);

        int npk = (int)pk0 + (int)pk1 + (int)pk2 + (int)pk3;
        sc += npk;
        sy += i * npk;
        sx += col0 * npk + (int)pk1 + 2 * (int)pk2 + 3 * (int)pk3;

        A = B; B = C;
        aL = bL; bL = cL;
        aR = bR; bR = cR;
    }

    // warp-wide reduction (both LANE_W=16 groups target the same batch n)
    sy = __reduce_add_sync(0xFFFFFFFFu, sy);
    sx = __reduce_add_sync(0xFFFFFFFFu, sx);
    sc = __reduce_add_sync(0xFFFFFFFFu, sc);
    if (lane == 0 && sc) {
        atomicAdd(&g_acc[n][0], R * sy);
        atomicAdd(&g_acc[n][1], R * sx);
        atomicAdd(&g_acc[n][2], sc);
    }
}

// ---------------------------------------------------------------------------
// Single fused kernel: peak detection (all 3 levels) + last-block finalize.
// Warp-work map (global warp id w = blockIdx.x*8 + warpInBlock, 2688 total):
//   [0,2048):    p1 (256x256): n=w>>5; sub=w&31: col_strip=sub&1, row_strip=sub>>1
//   [2048,2560): p2 (128x128): t=w-2048: n=t>>3, row_strip=t&7
//   [2560,2688): p3 (64x64):   t=w-2560: n=t>>1, rs=t&1; two 16-lane groups,
//                              each a 16-row segment (seg = rs*2 + group)
// ---------------------------------------------------------------------------
__global__ void __launch_bounds__(256) offset_loss_kernel(
    const float* __restrict__ p1,
    const float* __restrict__ p2,
    const float* __restrict__ p3,
    const float* __restrict__ target,
    float* __restrict__ out)
{
    const int tid = threadIdx.x;

    // Block 0 computes target center sums first (hidden under other blocks' work).
    if (blockIdx.x == 0) {
        const int n = tid >> 2;
        const int q = tid & 3;
        const float* tb = target + (size_t)n * 32 * 5 + q * 8 * 5;
        float t0 = 0.f, t1 = 0.f;
#pragma unroll
        for (int k = 0; k < 8; k++) {
            const float* b = tb + k * 5;
            t0 += (b[0] + b[2]) * 0.5f;
            t1 += (b[1] + b[3]) * 0.5f;
        }
        t0 += __shfl_xor_sync(0xFFFFFFFFu, t0, 1);
        t1 += __shfl_xor_sync(0xFFFFFFFFu, t1, 1);
        t0 += __shfl_xor_sync(0xFFFFFFFFu, t0, 2);
        t1 += __shfl_xor_sync(0xFFFFFFFFu, t1, 2);
        if (q == 0) {
            g_ts[n][0] = t0;
            g_ts[n][1] = t1;
            // Fence by the WRITING thread so these stores are globally ordered
            // before this block's later g_done arrival.
            __threadfence();
        }
    }

    // Strip work.
    const int w = blockIdx.x * 8 + (tid >> 5);
    if (w < 2048) {
        const int n = w >> 5;
        const int sub = w & 31;
        const int cs = sub & 1;
        const int rs = sub >> 1;
        const int i_begin = 1 + rs * 16;
        const int i_end = min(i_begin + 15, 254);
        const float* img = p1 + ((size_t)n * 3 + 2) * 65536;
        process_strip<256, 4, 32>(img, n, i_begin, i_end, cs * 128);
    } else if (w < 2560) {
        const int t = w - 2048;
        const int n = t >> 3;
        const int rs = t & 7;
        const int i_begin = 1 + rs * 16;
        const int i_end = min(i_begin + 15, 126);
        const float* img = p2 + ((size_t)n * 3 + 2) * 16384;
        process_strip<128, 8, 32>(img, n, i_begin, i_end, 0);
    } else {
        const int t = w - 2560;
        const int n = t >> 1;
        const int rs = t & 1;
        const int group = (tid & 31) >> 4;
        const int seg = rs * 2 + group;
        const int i_begin = 1 + seg * 16;
        const int i_end = min(i_begin + 15, 62);
        const float* img = p3 + ((size_t)n * 3 + 2) * 4096;
        process_strip<64, 16, 16>(img, n, i_begin, i_end, 0);
    }

    // Arrival: last block finalizes. (Per-warp g_acc atomics above are globally
    // coherent at L2; g_ts stores fenced by their writers; tid 0's fence orders
    // its own view before the ticket.)
    __shared__ int s_last;
    __syncthreads();
    if (tid == 0) {
        __threadfence();
        const int ticket = atomicAdd(&g_done, 1);
        s_last = (ticket == gridDim.x - 1) ? 1 : 0;
    }
    __syncthreads();
    if (!s_last) return;

    // ---- finalize (one block, 256 threads; only threads 0..63 carry data) ----
    __threadfence();

    float off0 = 0.f, off1 = 0.f, cs0 = 0.f, cs1 = 0.f, ts0 = 0.f, ts1 = 0.f;
    int cnt = 0;
    if (tid < 64) {
        volatile int* acc = &g_acc[tid][0];
        const float c0 = (float)acc[0];   // center_sum[:,0]
        const float c1 = (float)acc[1];   // center_sum[:,1]
        cnt = acc[2];
        volatile float* ts = &g_ts[tid][0];
        ts0 = ts[0]; ts1 = ts[1];

        const float d0 = fabsf(c0 - ts0);
        const float d1 = fabsf(c1 - ts1);
        off0 = (d0 < 1.f) ? 0.5f * d0 * d0 : d0 - 0.5f;
        off1 = (d1 < 1.f) ? 0.5f * d1 * d1 : d1 - 0.5f;
        cs0 = c0; cs1 = c1;

        // reset accumulators for the next graph replay
        acc[0] = 0; acc[1] = 0; acc[2] = 0;
    }

    // reduce over 64 active threads (2 full warps; others contribute zeros)
#pragma unroll
    for (int d = 16; d > 0; d >>= 1) {
        off0 += __shfl_down_sync(0xFFFFFFFFu, off0, d);
        off1 += __shfl_down_sync(0xFFFFFFFFu, off1, d);
        cs0  += __shfl_down_sync(0xFFFFFFFFu, cs0, d);
        cs1  += __shfl_down_sync(0xFFFFFFFFu, cs1, d);
        ts0  += __shfl_down_sync(0xFFFFFFFFu, ts0, d);
        ts1  += __shfl_down_sync(0xFFFFFFFFu, ts1, d);
        cnt  += __shfl_down_sync(0xFFFFFFFFu, cnt, d);
    }
    __shared__ float sh[2][6];
    __shared__ int shc[2];
    if (tid < 64 && (tid & 31) == 0) {
        const int wg = tid >> 5;
        sh[wg][0] = off0; sh[wg][1] = off1; sh[wg][2] = cs0;
        sh[wg][3] = cs1;  sh[wg][4] = ts0;  sh[wg][5] = ts1;
        shc[wg] = cnt;
    }
    __syncthreads();
    if (tid == 0) {
        const float OFF0 = sh[0][0] + sh[1][0];
        const float OFF1 = sh[0][1] + sh[1][1];
        const float CS0  = sh[0][2] + sh[1][2];
        const float CS1  = sh[0][3] + sh[1][3];
        const float TS0  = sh[0][4] + sh[1][4];
        const float TS1  = sh[0][5] + sh[1][5];
        const float PSUM = (float)(shc[0] + shc[1]);
        out[0] = (OFF0 / fabsf(OFF0) * (CS0 - TS0) +
                  OFF1 / fabsf(OFF1) * (CS1 - TS1)) / PSUM;
        g_done = 0;   // reset arrival counter for next replay
    }
}

extern "C" void kernel_launch(void* const* d_in, const int* in_sizes, int n_in,
                              void* d_out, int out_size) {
    const float *p1 = nullptr, *p2 = nullptr, *p3 = nullptr, *tg = nullptr;
    for (int k = 0; k < n_in; k++) {
        switch (in_sizes[k]) {
            case 64 * 3 * 256 * 256: p1 = (const float*)d_in[k]; break;
            case 64 * 3 * 128 * 128: p2 = (const float*)d_in[k]; break;
            case 64 * 3 * 64 * 64:   p3 = (const float*)d_in[k]; break;
            case 64 * 32 * 5:        tg = (const float*)d_in[k]; break;
            default: break;
        }
    }

    // 2688 warps = 336 blocks * 8 warps; single fused launch.
    offset_loss_kernel<<<336, 256>>>(p1, p2, p3, tg, (float*)d_out);
}